// round 16
// baseline (speedup 1.0000x reference)
#include <cuda_runtime.h>
#include <cuda_bf16.h>
#include <math.h>
#include <stdint.h>

#define HSZ   1024
#define NHEADS 16
#define HDIM  64
#define BATCH 2
#define SEQ   2048
#define NTOK  (BATCH*SEQ)   /* 4096 */

// -------- scratch (allocation-free rule: __device__ globals) --------
__device__ __nv_bfloat16 g_xh[(size_t)NTOK * HSZ];
__device__ __nv_bfloat16 g_xl[(size_t)NTOK * HSZ];
__device__ float         g_gate[NTOK];
__device__ __nv_bfloat16 g_wqh[(size_t)3 * HSZ * HSZ];
__device__ __nv_bfloat16 g_wql[(size_t)3 * HSZ * HSZ];
__device__ __nv_bfloat16 g_woh[(size_t)HSZ * HSZ];
__device__ __nv_bfloat16 g_wol[(size_t)HSZ * HSZ];
__device__ __nv_bfloat16 g_qkvh[(size_t)NTOK * 3 * HSZ];
__device__ __nv_bfloat16 g_qkvl[(size_t)NTOK * 3 * HSZ];
__device__ __nv_bfloat16 g_atth[(size_t)NTOK * HSZ];
__device__ __nv_bfloat16 g_attl[(size_t)NTOK * HSZ];

#define MMA_BF16(c, a, b) \
    asm volatile("mma.sync.aligned.m16n8k16.row.col.f32.bf16.bf16.f32 " \
        "{%0,%1,%2,%3}, {%4,%5,%6,%7}, {%8,%9}, {%0,%1,%2,%3};" \
        : "+f"((c)[0]), "+f"((c)[1]), "+f"((c)[2]), "+f"((c)[3]) \
        : "r"((a)[0]), "r"((a)[1]), "r"((a)[2]), "r"((a)[3]), \
          "r"((b)[0]), "r"((b)[1]))

__device__ __forceinline__ uint32_t pack2bf(float a, float b) {
    __nv_bfloat162 t = __floats2bfloat162_rn(a, b);
    return *(uint32_t*)&t;
}

// ============================================================
// Kernel 0: fp32 -> bf16 hi/lo splitter (weights)
// ============================================================
__global__ __launch_bounds__(256) void wsplit(
    const float* __restrict__ w, __nv_bfloat16* __restrict__ wh,
    __nv_bfloat16* __restrict__ wl, int n4)
{
    const int i = blockIdx.x * 256 + threadIdx.x;
    if (i >= n4) return;
    float4 a = ((const float4*)w)[i];
    __nv_bfloat16 h0 = __float2bfloat16(a.x);
    __nv_bfloat16 h1 = __float2bfloat16(a.y);
    __nv_bfloat16 h2 = __float2bfloat16(a.z);
    __nv_bfloat16 h3 = __float2bfloat16(a.w);
    *(uint32_t*)&wh[i * 4 + 0] = pack2bf(__bfloat162float(h0), __bfloat162float(h1));
    *(uint32_t*)&wh[i * 4 + 2] = pack2bf(__bfloat162float(h2), __bfloat162float(h3));
    *(uint32_t*)&wl[i * 4 + 0] = pack2bf(a.x - __bfloat162float(h0), a.y - __bfloat162float(h1));
    *(uint32_t*)&wl[i * 4 + 2] = pack2bf(a.z - __bfloat162float(h2), a.w - __bfloat162float(h3));
}

// ============================================================
// Kernel 1: LayerNorm + entropy gate; writes xn as bf16 hi/lo
// ============================================================
__global__ __launch_bounds__(256) void ln_gate_kernel(
    const float* __restrict__ x,
    const float* __restrict__ lng,
    const float* __restrict__ lnb,
    const float* __restrict__ w_ent,
    const float* __restrict__ b_ent)
{
    __shared__ float sbuf[8];
    const int t   = blockIdx.x;
    const int tid = threadIdx.x;
    const float* xr = x + (size_t)t * HSZ;

    float4 v = ((const float4*)xr)[tid];
    float s = v.x + v.y + v.z + v.w;
#pragma unroll
    for (int off = 16; off; off >>= 1) s += __shfl_xor_sync(0xffffffffu, s, off);
    if ((tid & 31) == 0) sbuf[tid >> 5] = s;
    __syncthreads();
    float tot = 0.f;
#pragma unroll
    for (int i = 0; i < 8; i++) tot += sbuf[i];
    __syncthreads();
    const float mu = tot * (1.f / HSZ);

    float d0 = v.x - mu, d1 = v.y - mu, d2 = v.z - mu, d3 = v.w - mu;
    float s2 = d0 * d0 + d1 * d1 + d2 * d2 + d3 * d3;
#pragma unroll
    for (int off = 16; off; off >>= 1) s2 += __shfl_xor_sync(0xffffffffu, s2, off);
    if ((tid & 31) == 0) sbuf[tid >> 5] = s2;
    __syncthreads();
    float tot2 = 0.f;
#pragma unroll
    for (int i = 0; i < 8; i++) tot2 += sbuf[i];
    __syncthreads();
    const float rstd = rsqrtf(tot2 * (1.f / HSZ) + 1e-6f);

    float4 lg = ((const float4*)lng)[tid];
    float4 lb = ((const float4*)lnb)[tid];
    float4 we = ((const float4*)w_ent)[tid];
    const float xn0 = d0 * rstd * lg.x + lb.x;
    const float xn1 = d1 * rstd * lg.y + lb.y;
    const float xn2 = d2 * rstd * lg.z + lb.z;
    const float xn3 = d3 * rstd * lg.w + lb.w;

    __nv_bfloat16 h0 = __float2bfloat16(xn0);
    __nv_bfloat16 h1 = __float2bfloat16(xn1);
    __nv_bfloat16 h2 = __float2bfloat16(xn2);
    __nv_bfloat16 h3 = __float2bfloat16(xn3);
    const size_t o = (size_t)t * HSZ + tid * 4;
    *(uint32_t*)&g_xh[o + 0] = pack2bf(__bfloat162float(h0), __bfloat162float(h1));
    *(uint32_t*)&g_xh[o + 2] = pack2bf(__bfloat162float(h2), __bfloat162float(h3));
    *(uint32_t*)&g_xl[o + 0] = pack2bf(xn0 - __bfloat162float(h0), xn1 - __bfloat162float(h1));
    *(uint32_t*)&g_xl[o + 2] = pack2bf(xn2 - __bfloat162float(h2), xn3 - __bfloat162float(h3));

    float e = xn0 * we.x + xn1 * we.y + xn2 * we.z + xn3 * we.w;
#pragma unroll
    for (int off = 16; off; off >>= 1) e += __shfl_xor_sync(0xffffffffu, e, off);
    if ((tid & 31) == 0) sbuf[tid >> 5] = e;
    __syncthreads();
    if (tid == 0) {
        float et = 0.f;
#pragma unroll
        for (int i = 0; i < 8; i++) et += sbuf[i];
        float gt = 1.f / (1.f + __expf(-(et + b_ent[0])));
        g_gate[t] = fminf(fmaxf(gt, 0.1f), 2.0f);
    }
}

// ============================================================
// Kernel 2: bf16x3 GEMM on pre-split inputs, cp.async 2-stage.
// Compensation MMAs reordered term-major: consecutive MMAs hit
// different accumulators (4-deep independence).
// ============================================================
#define GSTR 40
#define GTILE (128 * GSTR)
#define GSTAGE (4 * GTILE)
#define G_SMEM (2 * GSTAGE * 2)   /* 81920 B */

__global__ __launch_bounds__(256, 2) void bf16x3_gemm2(
    const __nv_bfloat16* __restrict__ Ah_, const __nv_bfloat16* __restrict__ Al_,
    const __nv_bfloat16* __restrict__ Bh_, const __nv_bfloat16* __restrict__ Bl_,
    const float* __restrict__ bias, const float* __restrict__ gate, int gcol0,
    float* __restrict__ Cf, __nv_bfloat16* __restrict__ Ch, __nv_bfloat16* __restrict__ Cl,
    int M, int N, int K, float alpha)
{
    extern __shared__ __nv_bfloat16 sg[];
    const int tid = threadIdx.x;
    const int wid = tid >> 5, lane = tid & 31;
    const int g = lane >> 2, tg = lane & 3;
    const int wm = (wid >> 2) * 64, wn = (wid & 3) * 32;
    const int m0 = blockIdx.y * 128, n0 = blockIdx.x * 128;

    const __nv_bfloat16* gsrc[4] = {Ah_, Al_, Bh_, Bl_};
    const int rbase[4] = {m0, m0, n0, n0};

    float acc[4][4][4];
#pragma unroll
    for (int mt = 0; mt < 4; mt++)
#pragma unroll
        for (int nt = 0; nt < 4; nt++)
#pragma unroll
            for (int q = 0; q < 4; q++) acc[mt][nt][q] = 0.f;

    const int NC = K >> 5;

#define G_FILL(ST, K0) do { \
    __nv_bfloat16* stp = sg + (ST) * GSTAGE; \
    _Pragma("unroll") \
    for (int sel = 0; sel < 4; sel++) { \
        _Pragma("unroll") \
        for (int half = 0; half < 2; half++) { \
            const int id = tid + half * 256; \
            const int row = id >> 2, ch = id & 3; \
            const __nv_bfloat16* src = gsrc[sel] + (size_t)(rbase[sel] + row) * K + (K0) + ch * 8; \
            uint32_t dst = (uint32_t)__cvta_generic_to_shared(stp + sel * GTILE + row * GSTR + ch * 8); \
            asm volatile("cp.async.cg.shared.global [%0], [%1], 16;" :: "r"(dst), "l"(src)); \
        } \
    } \
    asm volatile("cp.async.commit_group;" ::: "memory"); \
} while (0)

    G_FILL(0, 0);

    for (int c = 0; c < NC; c++) {
        if (c + 1 < NC) {
            G_FILL((c + 1) & 1, (c + 1) << 5);
            asm volatile("cp.async.wait_group 1;" ::: "memory");
        } else {
            asm volatile("cp.async.wait_group 0;" ::: "memory");
        }
        __syncthreads();

        const __nv_bfloat16* Ah = sg + (c & 1) * GSTAGE;
        const __nv_bfloat16* Al = Ah + GTILE;
        const __nv_bfloat16* Bh = Ah + 2 * GTILE;
        const __nv_bfloat16* Bl = Ah + 3 * GTILE;

#pragma unroll
        for (int kk = 0; kk < 32; kk += 16) {
            uint32_t ah[4][4], al[4][4];
#pragma unroll
            for (int mt = 0; mt < 4; mt++) {
                const int o0 = (wm + mt * 16 + g) * GSTR + kk + tg * 2;
                const int o1 = o0 + 8 * GSTR;
                ah[mt][0] = *(const uint32_t*)&Ah[o0];
                ah[mt][1] = *(const uint32_t*)&Ah[o1];
                ah[mt][2] = *(const uint32_t*)&Ah[o0 + 8];
                ah[mt][3] = *(const uint32_t*)&Ah[o1 + 8];
                al[mt][0] = *(const uint32_t*)&Al[o0];
                al[mt][1] = *(const uint32_t*)&Al[o1];
                al[mt][2] = *(const uint32_t*)&Al[o0 + 8];
                al[mt][3] = *(const uint32_t*)&Al[o1 + 8];
            }
#pragma unroll
            for (int nt = 0; nt < 4; nt++) {
                uint32_t bh[2], bl[2];
                const int ob = (wn + nt * 8 + g) * GSTR + kk + tg * 2;
                bh[0] = *(const uint32_t*)&Bh[ob];
                bh[1] = *(const uint32_t*)&Bh[ob + 8];
                bl[0] = *(const uint32_t*)&Bl[ob];
                bl[1] = *(const uint32_t*)&Bl[ob + 8];
                // term-major: consecutive MMAs always hit different acc
#pragma unroll
                for (int mt = 0; mt < 4; mt++) MMA_BF16(acc[mt][nt], ah[mt], bh);
#pragma unroll
                for (int mt = 0; mt < 4; mt++) MMA_BF16(acc[mt][nt], ah[mt], bl);
#pragma unroll
                for (int mt = 0; mt < 4; mt++) MMA_BF16(acc[mt][nt], al[mt], bh);
            }
        }
        __syncthreads();
    }

    // epilogue
#pragma unroll
    for (int mt = 0; mt < 4; mt++) {
        const int r0 = m0 + wm + mt * 16 + g;
#pragma unroll
        for (int nt = 0; nt < 4; nt++) {
            const int col = n0 + wn + nt * 8 + tg * 2;
            float v0 = acc[mt][nt][0] + bias[col];
            float v1 = acc[mt][nt][1] + bias[col + 1];
            float v2 = acc[mt][nt][2] + bias[col];
            float v3 = acc[mt][nt][3] + bias[col + 1];
            if (Cf) {
                float2 o;
                o.x = alpha * v0; o.y = alpha * v1;
                *(float2*)(Cf + (size_t)r0 * N + col) = o;
                o.x = alpha * v2; o.y = alpha * v3;
                *(float2*)(Cf + (size_t)(r0 + 8) * N + col) = o;
            } else {
                if (gate && col >= gcol0) {
                    const float g0 = gate[r0], g1 = gate[r0 + 8];
                    v0 *= g0; v1 *= g0; v2 *= g1; v3 *= g1;
                }
                __nv_bfloat16 h0 = __float2bfloat16(v0);
                __nv_bfloat16 h1 = __float2bfloat16(v1);
                __nv_bfloat16 h2 = __float2bfloat16(v2);
                __nv_bfloat16 h3 = __float2bfloat16(v3);
                const size_t oA = (size_t)r0 * N + col;
                const size_t oB = (size_t)(r0 + 8) * N + col;
                *(uint32_t*)&Ch[oA] = pack2bf(__bfloat162float(h0), __bfloat162float(h1));
                *(uint32_t*)&Ch[oB] = pack2bf(__bfloat162float(h2), __bfloat162float(h3));
                *(uint32_t*)&Cl[oA] = pack2bf(v0 - __bfloat162float(h0), v1 - __bfloat162float(h1));
                *(uint32_t*)&Cl[oB] = pack2bf(v2 - __bfloat162float(h2), v3 - __bfloat162float(h3));
            }
        }
    }
}

// ============================================================
// Kernel 3: mma.sync causal flash attention on pre-split bf16 qkv.
// Q persistent in smem (fragments reloaded per ds-step -> low regs),
// 2 CTAs/SM; QK/PV compensation MMAs interleaved across nt pairs.
// ============================================================
#define KSTR 72
#define VSTR 72
#define QELEM (128 * KSTR)
#define ATT_SMEM ((2 * 128 * KSTR + 4 * 64 * KSTR) * 2)   /* 73728 B */

__global__ __launch_bounds__(256, 2) void attn_mma(void)
{
    extern __shared__ __nv_bfloat16 sb[];
    __nv_bfloat16* Qh = sb;                       // [128][72]
    __nv_bfloat16* Ql = sb + QELEM;               // [128][72]
    __nv_bfloat16* Kh = sb + 2 * QELEM;           // [64][72]
    __nv_bfloat16* Kl = Kh + 64 * KSTR;
    __nv_bfloat16* Vh = Kl + 64 * KSTR;           // transposed [d][key]
    __nv_bfloat16* Vl = Vh + 64 * KSTR;

    const int qt  = gridDim.x - 1 - blockIdx.x;
    const int h   = blockIdx.y, b = blockIdx.z;
    const int tid = threadIdx.x;
    const int wid = tid >> 5;
    const int lane = tid & 31;
    const int gi = lane >> 2;
    const int tg = lane & 3;
    const int q0 = qt * 128;
    const float scl = 1.25f;

    // ---- stage Q into persistent smem region ----
#pragma unroll
    for (int i = 0; i < 8; i++) {
        const int idx = tid + (i & 3) * 256;
        const int row = idx >> 3, c8 = idx & 7;
        const __nv_bfloat16* src = (i < 4 ? g_qkvh : g_qkvl)
            + (size_t)(b * SEQ + q0 + row) * 3072 + h * 64 + c8 * 8;
        __nv_bfloat16* dst = (i < 4 ? Qh : Ql) + row * KSTR + c8 * 8;
        *(uint4*)dst = *(const uint4*)src;
    }

    float m0v = -INFINITY, m1v = -INFINITY, l0v = 0.f, l1v = 0.f;
    float acc_o[8][4];
#pragma unroll
    for (int nt = 0; nt < 8; nt++)
#pragma unroll
        for (int q = 0; q < 4; q++) acc_o[nt][q] = 0.f;

    const int r0q  = 16 * wid + gi;
    const int row0 = q0 + r0q;
    const int row1 = row0 + 8;
    const int rmax = q0 + 16 * wid + 15;
    const int nkt = 2 * qt + 2;

    for (int kt = 0; kt < nkt; kt++) {
        const int k0 = kt * 64;

        // ---- K fill ----
#pragma unroll
        for (int i = 0; i < 4; i++) {
            const int idx = tid + (i & 1) * 256;
            const int key = idx >> 3, c8 = idx & 7;
            const __nv_bfloat16* src = (i < 2 ? g_qkvh : g_qkvl)
                + (size_t)(b * SEQ + k0 + key) * 3072 + 1024 + h * 64 + c8 * 8;
            __nv_bfloat16* dst = (i < 2 ? Kh : Kl) + key * KSTR + c8 * 8;
            *(uint4*)dst = *(const uint4*)src;
        }
        // ---- V fill: key-pair transpose ----
        {
            const int kp = tid & 31, c8 = tid >> 5;
#pragma unroll
            for (int i = 0; i < 2; i++) {
                const __nv_bfloat16* src = (i == 0 ? g_qkvh : g_qkvl)
                    + (size_t)(b * SEQ + k0 + 2 * kp) * 3072 + 2048 + h * 64 + c8 * 8;
                uint4 ua = *(const uint4*)src;
                uint4 ub = *(const uint4*)(src + 3072);
                const __nv_bfloat16* va = (const __nv_bfloat16*)&ua;
                const __nv_bfloat16* vb = (const __nv_bfloat16*)&ub;
                __nv_bfloat16* Vt = (i == 0 ? Vh : Vl);
#pragma unroll
                for (int j = 0; j < 8; j++) {
                    __nv_bfloat162 p;
                    p.x = va[j]; p.y = vb[j];
                    *(__nv_bfloat162*)&Vt[(c8 * 8 + j) * VSTR + 2 * kp] = p;
                }
            }
        }
        __syncthreads();

        if (k0 <= rmax) {
            // ---- QK^T (bf16x3), Q frags reloaded per ds ----
            float s[8][4];
#pragma unroll
            for (int nt = 0; nt < 8; nt++)
#pragma unroll
                for (int q = 0; q < 4; q++) s[nt][q] = 0.f;

#pragma unroll
            for (int ds = 0; ds < 4; ds++) {
                const int kq = ds * 16 + tg * 2;
                uint32_t qh[4], ql[4];
                qh[0] = *(const uint32_t*)&Qh[r0q * KSTR + kq];
                qh[1] = *(const uint32_t*)&Qh[(r0q + 8) * KSTR + kq];
                qh[2] = *(const uint32_t*)&Qh[r0q * KSTR + kq + 8];
                qh[3] = *(const uint32_t*)&Qh[(r0q + 8) * KSTR + kq + 8];
                ql[0] = *(const uint32_t*)&Ql[r0q * KSTR + kq];
                ql[1] = *(const uint32_t*)&Ql[(r0q + 8) * KSTR + kq];
                ql[2] = *(const uint32_t*)&Ql[r0q * KSTR + kq + 8];
                ql[3] = *(const uint32_t*)&Ql[(r0q + 8) * KSTR + kq + 8];
#pragma unroll
                for (int nt = 0; nt < 8; nt += 2) {
                    uint32_t b0h[2], b0l[2], b1h[2], b1l[2];
                    const int o0 = (nt * 8 + gi) * KSTR + kq;
                    const int o1 = ((nt + 1) * 8 + gi) * KSTR + kq;
                    b0h[0] = *(const uint32_t*)&Kh[o0];
                    b0h[1] = *(const uint32_t*)&Kh[o0 + 8];
                    b1h[0] = *(const uint32_t*)&Kh[o1];
                    b1h[1] = *(const uint32_t*)&Kh[o1 + 8];
                    b0l[0] = *(const uint32_t*)&Kl[o0];
                    b0l[1] = *(const uint32_t*)&Kl[o0 + 8];
                    b1l[0] = *(const uint32_t*)&Kl[o1];
                    b1l[1] = *(const uint32_t*)&Kl[o1 + 8];
                    MMA_BF16(s[nt],     qh, b0h);
                    MMA_BF16(s[nt + 1], qh, b1h);
                    MMA_BF16(s[nt],     qh, b0l);
                    MMA_BF16(s[nt + 1], qh, b1l);
                    MMA_BF16(s[nt],     ql, b0h);
                    MMA_BF16(s[nt + 1], ql, b1h);
                }
            }

#pragma unroll
            for (int nt = 0; nt < 8; nt++)
#pragma unroll
                for (int q = 0; q < 4; q++) s[nt][q] *= scl;
            if (kt >= 2 * qt) {
#pragma unroll
                for (int nt = 0; nt < 8; nt++) {
                    const int c0 = k0 + nt * 8 + tg * 2;
                    if (c0     > row0) s[nt][0] = -INFINITY;
                    if (c0 + 1 > row0) s[nt][1] = -INFINITY;
                    if (c0     > row1) s[nt][2] = -INFINITY;
                    if (c0 + 1 > row1) s[nt][3] = -INFINITY;
                }
            }

            // ---- online softmax ----
            float mx0 = -INFINITY, mx1 = -INFINITY;
#pragma unroll
            for (int nt = 0; nt < 8; nt++) {
                mx0 = fmaxf(mx0, fmaxf(s[nt][0], s[nt][1]));
                mx1 = fmaxf(mx1, fmaxf(s[nt][2], s[nt][3]));
            }
            mx0 = fmaxf(mx0, __shfl_xor_sync(0xffffffffu, mx0, 1));
            mx0 = fmaxf(mx0, __shfl_xor_sync(0xffffffffu, mx0, 2));
            mx1 = fmaxf(mx1, __shfl_xor_sync(0xffffffffu, mx1, 1));
            mx1 = fmaxf(mx1, __shfl_xor_sync(0xffffffffu, mx1, 2));

            const float nm0 = fmaxf(m0v, mx0);
            const float nm1 = fmaxf(m1v, mx1);
            const float al0 = __expf(m0v - nm0);
            const float al1 = __expf(m1v - nm1);
            float rs0 = 0.f, rs1 = 0.f;
#pragma unroll
            for (int nt = 0; nt < 8; nt++) {
                s[nt][0] = __expf(s[nt][0] - nm0);
                s[nt][1] = __expf(s[nt][1] - nm0);
                s[nt][2] = __expf(s[nt][2] - nm1);
                s[nt][3] = __expf(s[nt][3] - nm1);
                rs0 += s[nt][0] + s[nt][1];
                rs1 += s[nt][2] + s[nt][3];
            }
            rs0 += __shfl_xor_sync(0xffffffffu, rs0, 1);
            rs0 += __shfl_xor_sync(0xffffffffu, rs0, 2);
            rs1 += __shfl_xor_sync(0xffffffffu, rs1, 1);
            rs1 += __shfl_xor_sync(0xffffffffu, rs1, 2);
            l0v = l0v * al0 + rs0;
            l1v = l1v * al1 + rs1;
            m0v = nm0; m1v = nm1;
#pragma unroll
            for (int nt = 0; nt < 8; nt++) {
                acc_o[nt][0] *= al0; acc_o[nt][1] *= al0;
                acc_o[nt][2] *= al1; acc_o[nt][3] *= al1;
            }

            // ---- PV (bf16x3), interleaved across nt pairs ----
#pragma unroll
            for (int s4 = 0; s4 < 4; s4++) {
                uint32_t pa[4], pl[4];
                {
                    const float p00 = s[2 * s4][0],     p01 = s[2 * s4][1];
                    const float p02 = s[2 * s4][2],     p03 = s[2 * s4][3];
                    const float p10 = s[2 * s4 + 1][0], p11 = s[2 * s4 + 1][1];
                    const float p12 = s[2 * s4 + 1][2], p13 = s[2 * s4 + 1][3];
                    pa[0] = pack2bf(p00, p01);
                    pa[1] = pack2bf(p02, p03);
                    pa[2] = pack2bf(p10, p11);
                    pa[3] = pack2bf(p12, p13);
                    __nv_bfloat162* ph;
                    ph = (__nv_bfloat162*)&pa[0];
                    pl[0] = pack2bf(p00 - __bfloat162float(ph->x), p01 - __bfloat162float(ph->y));
                    ph = (__nv_bfloat162*)&pa[1];
                    pl[1] = pack2bf(p02 - __bfloat162float(ph->x), p03 - __bfloat162float(ph->y));
                    ph = (__nv_bfloat162*)&pa[2];
                    pl[2] = pack2bf(p10 - __bfloat162float(ph->x), p11 - __bfloat162float(ph->y));
                    ph = (__nv_bfloat162*)&pa[3];
                    pl[3] = pack2bf(p12 - __bfloat162float(ph->x), p13 - __bfloat162float(ph->y));
                }
                const int kk = s4 * 16 + tg * 2;
#pragma unroll
                for (int nt = 0; nt < 8; nt += 2) {
                    uint32_t b0h[2], b0l[2], b1h[2], b1l[2];
                    const int o0 = (nt * 8 + gi) * VSTR + kk;
                    const int o1 = ((nt + 1) * 8 + gi) * VSTR + kk;
                    b0h[0] = *(const uint32_t*)&Vh[o0];
                    b0h[1] = *(const uint32_t*)&Vh[o0 + 8];
                    b1h[0] = *(const uint32_t*)&Vh[o1];
                    b1h[1] = *(const uint32_t*)&Vh[o1 + 8];
                    b0l[0] = *(const uint32_t*)&Vl[o0];
                    b0l[1] = *(const uint32_t*)&Vl[o0 + 8];
                    b1l[0] = *(const uint32_t*)&Vl[o1];
                    b1l[1] = *(const uint32_t*)&Vl[o1 + 8];
                    MMA_BF16(acc_o[nt],     pa, b0h);
                    MMA_BF16(acc_o[nt + 1], pa, b1h);
                    MMA_BF16(acc_o[nt],     pa, b0l);
                    MMA_BF16(acc_o[nt + 1], pa, b1l);
                    MMA_BF16(acc_o[nt],     pl, b0h);
                    MMA_BF16(acc_o[nt + 1], pl, b1h);
                }
            }
        }
        __syncthreads();
    }

    // ---- epilogue: split output to bf16 hi/lo ----
    const float inv0 = 1.f / l0v;
    const float inv1 = 1.f / l1v;
#pragma unroll
    for (int nt = 0; nt < 8; nt++) {
        const int col = h * 64 + nt * 8 + tg * 2;
        const float o0 = acc_o[nt][0] * inv0, o1 = acc_o[nt][1] * inv0;
        const float o2 = acc_o[nt][2] * inv1, o3 = acc_o[nt][3] * inv1;
        __nv_bfloat16 h0 = __float2bfloat16(o0);
        __nv_bfloat16 h1 = __float2bfloat16(o1);
        __nv_bfloat16 h2 = __float2bfloat16(o2);
        __nv_bfloat16 h3 = __float2bfloat16(o3);
        const size_t oA = (size_t)(b * SEQ + row0) * HSZ + col;
        const size_t oB = (size_t)(b * SEQ + row1) * HSZ + col;
        *(uint32_t*)&g_atth[oA] = pack2bf(__bfloat162float(h0), __bfloat162float(h1));
        *(uint32_t*)&g_atth[oB] = pack2bf(__bfloat162float(h2), __bfloat162float(h3));
        *(uint32_t*)&g_attl[oA] = pack2bf(o0 - __bfloat162float(h0), o1 - __bfloat162float(h1));
        *(uint32_t*)&g_attl[oB] = pack2bf(o2 - __bfloat162float(h2), o3 - __bfloat162float(h3));
    }
}

// ============================================================
// host launcher
// ============================================================
extern "C" void kernel_launch(void* const* d_in, const int* in_sizes, int n_in,
                              void* d_out, int out_size)
{
    const float* x     = (const float*)d_in[0];
    const float* ln_g  = (const float*)d_in[1];
    const float* ln_b  = (const float*)d_in[2];
    const float* w_qkv = (const float*)d_in[3];
    const float* b_qkv = (const float*)d_in[4];
    const float* w_ent = (const float*)d_in[5];
    const float* b_ent = (const float*)d_in[6];
    const float* w_out = (const float*)d_in[7];
    const float* b_out = (const float*)d_in[8];
    float* out = (float*)d_out;

    void *p_xh, *p_xl, *p_gate, *p_wqh, *p_wql, *p_woh, *p_wol;
    void *p_qkvh, *p_qkvl, *p_atth, *p_attl;
    cudaGetSymbolAddress(&p_xh,   g_xh);
    cudaGetSymbolAddress(&p_xl,   g_xl);
    cudaGetSymbolAddress(&p_gate, g_gate);
    cudaGetSymbolAddress(&p_wqh,  g_wqh);
    cudaGetSymbolAddress(&p_wql,  g_wql);
    cudaGetSymbolAddress(&p_woh,  g_woh);
    cudaGetSymbolAddress(&p_wol,  g_wol);
    cudaGetSymbolAddress(&p_qkvh, g_qkvh);
    cudaGetSymbolAddress(&p_qkvl, g_qkvl);
    cudaGetSymbolAddress(&p_atth, g_atth);
    cudaGetSymbolAddress(&p_attl, g_attl);

    cudaFuncSetAttribute(bf16x3_gemm2, cudaFuncAttributeMaxDynamicSharedMemorySize, G_SMEM);
    cudaFuncSetAttribute(attn_mma, cudaFuncAttributeMaxDynamicSharedMemorySize, ATT_SMEM);

    // 0) pre-split weights
    wsplit<<<(3 * HSZ * HSZ / 4 + 255) / 256, 256>>>(
        w_qkv, (__nv_bfloat16*)p_wqh, (__nv_bfloat16*)p_wql, 3 * HSZ * HSZ / 4);
    wsplit<<<(HSZ * HSZ / 4 + 255) / 256, 256>>>(
        w_out, (__nv_bfloat16*)p_woh, (__nv_bfloat16*)p_wol, HSZ * HSZ / 4);

    // 1) LN + entropy gate (writes split xn)
    ln_gate_kernel<<<NTOK, 256>>>(x, ln_g, ln_b, w_ent, b_ent);

    // 2) QKV projection -> split bf16 qkv, gate folded into V cols
    bf16x3_gemm2<<<dim3(3 * HSZ / 128, NTOK / 128), 256, G_SMEM>>>(
        (const __nv_bfloat16*)p_xh, (const __nv_bfloat16*)p_xl,
        (const __nv_bfloat16*)p_wqh, (const __nv_bfloat16*)p_wql,
        b_qkv, (const float*)p_gate, 2048,
        nullptr, (__nv_bfloat16*)p_qkvh, (__nv_bfloat16*)p_qkvl,
        NTOK, 3 * HSZ, HSZ, 1.0f);

    // 3) attention
    attn_mma<<<dim3(SEQ / 128, NHEADS, BATCH), 256, ATT_SMEM>>>();

    // 4) output projection (fp32 out, alpha=0.1)
    bf16x3_gemm2<<<dim3(HSZ / 128, NTOK / 128), 256, G_SMEM>>>(
        (const __nv_bfloat16*)p_atth, (const __nv_bfloat16*)p_attl,
        (const __nv_bfloat16*)p_woh, (const __nv_bfloat16*)p_wol,
        b_out, nullptr, 1 << 30,
        out, nullptr, nullptr,
        NTOK, HSZ, HSZ, 0.1f);
}

// round 17
// speedup vs baseline: 1.0250x; 1.0250x over previous
#include <cuda_runtime.h>
#include <cuda_bf16.h>
#include <math.h>
#include <stdint.h>

#define HSZ   1024
#define NHEADS 16
#define HDIM  64
#define BATCH 2
#define SEQ   2048
#define NTOK  (BATCH*SEQ)   /* 4096 */

// -------- scratch (allocation-free rule: __device__ globals) --------
__device__ __nv_bfloat16 g_xh[(size_t)NTOK * HSZ];
__device__ __nv_bfloat16 g_xl[(size_t)NTOK * HSZ];
__device__ float         g_gate[NTOK];
__device__ __nv_bfloat16 g_wqh[(size_t)3 * HSZ * HSZ];
__device__ __nv_bfloat16 g_wql[(size_t)3 * HSZ * HSZ];
__device__ __nv_bfloat16 g_woh[(size_t)HSZ * HSZ];
__device__ __nv_bfloat16 g_wol[(size_t)HSZ * HSZ];
__device__ __nv_bfloat16 g_qkvh[(size_t)NTOK * 3 * HSZ];
__device__ __nv_bfloat16 g_qkvl[(size_t)NTOK * 3 * HSZ];
__device__ __nv_bfloat16 g_atth[(size_t)NTOK * HSZ];
__device__ __nv_bfloat16 g_attl[(size_t)NTOK * HSZ];

#define MMA_BF16(c, a, b) \
    asm volatile("mma.sync.aligned.m16n8k16.row.col.f32.bf16.bf16.f32 " \
        "{%0,%1,%2,%3}, {%4,%5,%6,%7}, {%8,%9}, {%0,%1,%2,%3};" \
        : "+f"((c)[0]), "+f"((c)[1]), "+f"((c)[2]), "+f"((c)[3]) \
        : "r"((a)[0]), "r"((a)[1]), "r"((a)[2]), "r"((a)[3]), \
          "r"((b)[0]), "r"((b)[1]))

__device__ __forceinline__ uint32_t pack2bf(float a, float b) {
    __nv_bfloat162 t = __floats2bfloat162_rn(a, b);
    return *(uint32_t*)&t;
}

// ============================================================
// Kernel 0: fp32 -> bf16 hi/lo splitter (weights)
// ============================================================
__global__ __launch_bounds__(256) void wsplit(
    const float* __restrict__ w, __nv_bfloat16* __restrict__ wh,
    __nv_bfloat16* __restrict__ wl, int n4)
{
    const int i = blockIdx.x * 256 + threadIdx.x;
    if (i >= n4) return;
    float4 a = ((const float4*)w)[i];
    __nv_bfloat16 h0 = __float2bfloat16(a.x);
    __nv_bfloat16 h1 = __float2bfloat16(a.y);
    __nv_bfloat16 h2 = __float2bfloat16(a.z);
    __nv_bfloat16 h3 = __float2bfloat16(a.w);
    *(uint32_t*)&wh[i * 4 + 0] = pack2bf(__bfloat162float(h0), __bfloat162float(h1));
    *(uint32_t*)&wh[i * 4 + 2] = pack2bf(__bfloat162float(h2), __bfloat162float(h3));
    *(uint32_t*)&wl[i * 4 + 0] = pack2bf(a.x - __bfloat162float(h0), a.y - __bfloat162float(h1));
    *(uint32_t*)&wl[i * 4 + 2] = pack2bf(a.z - __bfloat162float(h2), a.w - __bfloat162float(h3));
}

// ============================================================
// Kernel 1: LayerNorm + entropy gate; writes xn as bf16 hi/lo
// ============================================================
__global__ __launch_bounds__(256) void ln_gate_kernel(
    const float* __restrict__ x,
    const float* __restrict__ lng,
    const float* __restrict__ lnb,
    const float* __restrict__ w_ent,
    const float* __restrict__ b_ent)
{
    __shared__ float sbuf[8];
    const int t   = blockIdx.x;
    const int tid = threadIdx.x;
    const float* xr = x + (size_t)t * HSZ;

    float4 v = ((const float4*)xr)[tid];
    float s = v.x + v.y + v.z + v.w;
#pragma unroll
    for (int off = 16; off; off >>= 1) s += __shfl_xor_sync(0xffffffffu, s, off);
    if ((tid & 31) == 0) sbuf[tid >> 5] = s;
    __syncthreads();
    float tot = 0.f;
#pragma unroll
    for (int i = 0; i < 8; i++) tot += sbuf[i];
    __syncthreads();
    const float mu = tot * (1.f / HSZ);

    float d0 = v.x - mu, d1 = v.y - mu, d2 = v.z - mu, d3 = v.w - mu;
    float s2 = d0 * d0 + d1 * d1 + d2 * d2 + d3 * d3;
#pragma unroll
    for (int off = 16; off; off >>= 1) s2 += __shfl_xor_sync(0xffffffffu, s2, off);
    if ((tid & 31) == 0) sbuf[tid >> 5] = s2;
    __syncthreads();
    float tot2 = 0.f;
#pragma unroll
    for (int i = 0; i < 8; i++) tot2 += sbuf[i];
    __syncthreads();
    const float rstd = rsqrtf(tot2 * (1.f / HSZ) + 1e-6f);

    float4 lg = ((const float4*)lng)[tid];
    float4 lb = ((const float4*)lnb)[tid];
    float4 we = ((const float4*)w_ent)[tid];
    const float xn0 = d0 * rstd * lg.x + lb.x;
    const float xn1 = d1 * rstd * lg.y + lb.y;
    const float xn2 = d2 * rstd * lg.z + lb.z;
    const float xn3 = d3 * rstd * lg.w + lb.w;

    __nv_bfloat16 h0 = __float2bfloat16(xn0);
    __nv_bfloat16 h1 = __float2bfloat16(xn1);
    __nv_bfloat16 h2 = __float2bfloat16(xn2);
    __nv_bfloat16 h3 = __float2bfloat16(xn3);
    const size_t o = (size_t)t * HSZ + tid * 4;
    *(uint32_t*)&g_xh[o + 0] = pack2bf(__bfloat162float(h0), __bfloat162float(h1));
    *(uint32_t*)&g_xh[o + 2] = pack2bf(__bfloat162float(h2), __bfloat162float(h3));
    *(uint32_t*)&g_xl[o + 0] = pack2bf(xn0 - __bfloat162float(h0), xn1 - __bfloat162float(h1));
    *(uint32_t*)&g_xl[o + 2] = pack2bf(xn2 - __bfloat162float(h2), xn3 - __bfloat162float(h3));

    float e = xn0 * we.x + xn1 * we.y + xn2 * we.z + xn3 * we.w;
#pragma unroll
    for (int off = 16; off; off >>= 1) e += __shfl_xor_sync(0xffffffffu, e, off);
    if ((tid & 31) == 0) sbuf[tid >> 5] = e;
    __syncthreads();
    if (tid == 0) {
        float et = 0.f;
#pragma unroll
        for (int i = 0; i < 8; i++) et += sbuf[i];
        float gt = 1.f / (1.f + __expf(-(et + b_ent[0])));
        g_gate[t] = fminf(fmaxf(gt, 0.1f), 2.0f);
    }
}

// ============================================================
// Kernel 2: bf16x3 GEMM on pre-split inputs, cp.async 2-stage.
// (measured at the mma.sync ceiling ~300 TF/s — unchanged)
// ============================================================
#define GSTR 40
#define GTILE (128 * GSTR)
#define GSTAGE (4 * GTILE)
#define G_SMEM (2 * GSTAGE * 2)   /* 81920 B */

__global__ __launch_bounds__(256, 2) void bf16x3_gemm2(
    const __nv_bfloat16* __restrict__ Ah_, const __nv_bfloat16* __restrict__ Al_,
    const __nv_bfloat16* __restrict__ Bh_, const __nv_bfloat16* __restrict__ Bl_,
    const float* __restrict__ bias, const float* __restrict__ gate, int gcol0,
    float* __restrict__ Cf, __nv_bfloat16* __restrict__ Ch, __nv_bfloat16* __restrict__ Cl,
    int M, int N, int K, float alpha)
{
    extern __shared__ __nv_bfloat16 sg[];
    const int tid = threadIdx.x;
    const int wid = tid >> 5, lane = tid & 31;
    const int g = lane >> 2, tg = lane & 3;
    const int wm = (wid >> 2) * 64, wn = (wid & 3) * 32;
    const int m0 = blockIdx.y * 128, n0 = blockIdx.x * 128;

    const __nv_bfloat16* gsrc[4] = {Ah_, Al_, Bh_, Bl_};
    const int rbase[4] = {m0, m0, n0, n0};

    float acc[4][4][4];
#pragma unroll
    for (int mt = 0; mt < 4; mt++)
#pragma unroll
        for (int nt = 0; nt < 4; nt++)
#pragma unroll
            for (int q = 0; q < 4; q++) acc[mt][nt][q] = 0.f;

    const int NC = K >> 5;

#define G_FILL(ST, K0) do { \
    __nv_bfloat16* stp = sg + (ST) * GSTAGE; \
    _Pragma("unroll") \
    for (int sel = 0; sel < 4; sel++) { \
        _Pragma("unroll") \
        for (int half = 0; half < 2; half++) { \
            const int id = tid + half * 256; \
            const int row = id >> 2, ch = id & 3; \
            const __nv_bfloat16* src = gsrc[sel] + (size_t)(rbase[sel] + row) * K + (K0) + ch * 8; \
            uint32_t dst = (uint32_t)__cvta_generic_to_shared(stp + sel * GTILE + row * GSTR + ch * 8); \
            asm volatile("cp.async.cg.shared.global [%0], [%1], 16;" :: "r"(dst), "l"(src)); \
        } \
    } \
    asm volatile("cp.async.commit_group;" ::: "memory"); \
} while (0)

    G_FILL(0, 0);

    for (int c = 0; c < NC; c++) {
        if (c + 1 < NC) {
            G_FILL((c + 1) & 1, (c + 1) << 5);
            asm volatile("cp.async.wait_group 1;" ::: "memory");
        } else {
            asm volatile("cp.async.wait_group 0;" ::: "memory");
        }
        __syncthreads();

        const __nv_bfloat16* Ah = sg + (c & 1) * GSTAGE;
        const __nv_bfloat16* Al = Ah + GTILE;
        const __nv_bfloat16* Bh = Ah + 2 * GTILE;
        const __nv_bfloat16* Bl = Ah + 3 * GTILE;

#pragma unroll
        for (int kk = 0; kk < 32; kk += 16) {
            uint32_t ah[4][4], al[4][4];
#pragma unroll
            for (int mt = 0; mt < 4; mt++) {
                const int o0 = (wm + mt * 16 + g) * GSTR + kk + tg * 2;
                const int o1 = o0 + 8 * GSTR;
                ah[mt][0] = *(const uint32_t*)&Ah[o0];
                ah[mt][1] = *(const uint32_t*)&Ah[o1];
                ah[mt][2] = *(const uint32_t*)&Ah[o0 + 8];
                ah[mt][3] = *(const uint32_t*)&Ah[o1 + 8];
                al[mt][0] = *(const uint32_t*)&Al[o0];
                al[mt][1] = *(const uint32_t*)&Al[o1];
                al[mt][2] = *(const uint32_t*)&Al[o0 + 8];
                al[mt][3] = *(const uint32_t*)&Al[o1 + 8];
            }
#pragma unroll
            for (int nt = 0; nt < 4; nt++) {
                uint32_t bh[2], bl[2];
                const int ob = (wn + nt * 8 + g) * GSTR + kk + tg * 2;
                bh[0] = *(const uint32_t*)&Bh[ob];
                bh[1] = *(const uint32_t*)&Bh[ob + 8];
                bl[0] = *(const uint32_t*)&Bl[ob];
                bl[1] = *(const uint32_t*)&Bl[ob + 8];
#pragma unroll
                for (int mt = 0; mt < 4; mt++) MMA_BF16(acc[mt][nt], ah[mt], bh);
#pragma unroll
                for (int mt = 0; mt < 4; mt++) MMA_BF16(acc[mt][nt], ah[mt], bl);
#pragma unroll
                for (int mt = 0; mt < 4; mt++) MMA_BF16(acc[mt][nt], al[mt], bh);
            }
        }
        __syncthreads();
    }

    // epilogue
#pragma unroll
    for (int mt = 0; mt < 4; mt++) {
        const int r0 = m0 + wm + mt * 16 + g;
#pragma unroll
        for (int nt = 0; nt < 4; nt++) {
            const int col = n0 + wn + nt * 8 + tg * 2;
            float v0 = acc[mt][nt][0] + bias[col];
            float v1 = acc[mt][nt][1] + bias[col + 1];
            float v2 = acc[mt][nt][2] + bias[col];
            float v3 = acc[mt][nt][3] + bias[col + 1];
            if (Cf) {
                float2 o;
                o.x = alpha * v0; o.y = alpha * v1;
                *(float2*)(Cf + (size_t)r0 * N + col) = o;
                o.x = alpha * v2; o.y = alpha * v3;
                *(float2*)(Cf + (size_t)(r0 + 8) * N + col) = o;
            } else {
                if (gate && col >= gcol0) {
                    const float g0 = gate[r0], g1 = gate[r0 + 8];
                    v0 *= g0; v1 *= g0; v2 *= g1; v3 *= g1;
                }
                __nv_bfloat16 h0 = __float2bfloat16(v0);
                __nv_bfloat16 h1 = __float2bfloat16(v1);
                __nv_bfloat16 h2 = __float2bfloat16(v2);
                __nv_bfloat16 h3 = __float2bfloat16(v3);
                const size_t oA = (size_t)r0 * N + col;
                const size_t oB = (size_t)(r0 + 8) * N + col;
                *(uint32_t*)&Ch[oA] = pack2bf(__bfloat162float(h0), __bfloat162float(h1));
                *(uint32_t*)&Ch[oB] = pack2bf(__bfloat162float(h2), __bfloat162float(h3));
                *(uint32_t*)&Cl[oA] = pack2bf(v0 - __bfloat162float(h0), v1 - __bfloat162float(h1));
                *(uint32_t*)&Cl[oB] = pack2bf(v2 - __bfloat162float(h2), v3 - __bfloat162float(h3));
            }
        }
    }
}

// ============================================================
// Kernel 3: mma.sync causal flash attention (R14 register-Q base)
// + register-level prefetch of next K/V tile overlapping compute.
// QK^T = bf16x3; PV = bf16x3; gate pre-folded into V.
// ============================================================
#define KSTR 72
#define VSTR 72
#define ATT_SMEM (4 * 64 * 72 * 2)   /* 36864 B */

__global__ __launch_bounds__(256, 1) void attn_mma(void)
{
    extern __shared__ __nv_bfloat16 sb[];
    __nv_bfloat16* Kh = sb;
    __nv_bfloat16* Kl = sb + 64 * KSTR;
    __nv_bfloat16* Vh = sb + 2 * 64 * KSTR;   // transposed [d][key]
    __nv_bfloat16* Vl = sb + 3 * 64 * KSTR;

    const int qt  = gridDim.x - 1 - blockIdx.x;
    const int h   = blockIdx.y, b = blockIdx.z;
    const int tid = threadIdx.x;
    const int wid = tid >> 5;
    const int lane = tid & 31;
    const int gi = lane >> 2;
    const int tg = lane & 3;
    const int q0 = qt * 128;
    const float scl = 1.25f;

    // ---- stage Q (copy pre-split bf16), then load fragments ----
    {
        __nv_bfloat16* Qh = sb;
        __nv_bfloat16* Ql = sb + 128 * KSTR;
#pragma unroll
        for (int i = 0; i < 8; i++) {
            const int idx = tid + (i & 3) * 256;
            const int row = idx >> 3, c8 = idx & 7;
            const __nv_bfloat16* src = (i < 4 ? g_qkvh : g_qkvl)
                + (size_t)(b * SEQ + q0 + row) * 3072 + h * 64 + c8 * 8;
            __nv_bfloat16* dst = (i < 4 ? Qh : Ql) + row * KSTR + c8 * 8;
            *(uint4*)dst = *(const uint4*)src;
        }
    }
    __syncthreads();

    uint32_t qh[4][4], ql[4][4];
    {
        const __nv_bfloat16* Qh = sb;
        const __nv_bfloat16* Ql = sb + 128 * KSTR;
        const int r0 = 16 * wid + gi;
#pragma unroll
        for (int ds = 0; ds < 4; ds++) {
            const int k = ds * 16 + tg * 2;
            qh[ds][0] = *(const uint32_t*)&Qh[r0 * KSTR + k];
            qh[ds][1] = *(const uint32_t*)&Qh[(r0 + 8) * KSTR + k];
            qh[ds][2] = *(const uint32_t*)&Qh[r0 * KSTR + k + 8];
            qh[ds][3] = *(const uint32_t*)&Qh[(r0 + 8) * KSTR + k + 8];
            ql[ds][0] = *(const uint32_t*)&Ql[r0 * KSTR + k];
            ql[ds][1] = *(const uint32_t*)&Ql[(r0 + 8) * KSTR + k];
            ql[ds][2] = *(const uint32_t*)&Ql[r0 * KSTR + k + 8];
            ql[ds][3] = *(const uint32_t*)&Ql[(r0 + 8) * KSTR + k + 8];
        }
    }
    __syncthreads();

    float m0v = -INFINITY, m1v = -INFINITY, l0v = 0.f, l1v = 0.f;
    float acc_o[8][4];
#pragma unroll
    for (int nt = 0; nt < 8; nt++)
#pragma unroll
        for (int q = 0; q < 4; q++) acc_o[nt][q] = 0.f;

    const int row0 = q0 + 16 * wid + gi;
    const int row1 = row0 + 8;
    const int rmax = q0 + 16 * wid + 15;
    const int nkt = 2 * qt + 2;

    // index helpers (fixed per thread)
    const int kp = tid & 31, c8v = tid >> 5;

    // ---- prefetch tile 0 into registers ----
    uint4 pk[4];        // K: (Kh i0,i1), (Kl i0,i1)
    uint4 pva[2], pvb[2];  // V: [hi,lo] x (key 2kp, 2kp+1)
#pragma unroll
    for (int i = 0; i < 4; i++) {
        const int idx = tid + (i & 1) * 256;
        const int key = idx >> 3, c8 = idx & 7;
        pk[i] = *(const uint4*)((i < 2 ? g_qkvh : g_qkvl)
            + (size_t)(b * SEQ + key) * 3072 + 1024 + h * 64 + c8 * 8);
    }
#pragma unroll
    for (int i = 0; i < 2; i++) {
        const __nv_bfloat16* src = (i == 0 ? g_qkvh : g_qkvl)
            + (size_t)(b * SEQ + 2 * kp) * 3072 + 2048 + h * 64 + c8v * 8;
        pva[i] = *(const uint4*)src;
        pvb[i] = *(const uint4*)(src + 3072);
    }

    for (int kt = 0; kt < nkt; kt++) {
        const int k0 = kt * 64;

        // ---- store prefetched K/V registers to smem ----
#pragma unroll
        for (int i = 0; i < 4; i++) {
            const int idx = tid + (i & 1) * 256;
            const int key = idx >> 3, c8 = idx & 7;
            __nv_bfloat16* dst = (i < 2 ? Kh : Kl) + key * KSTR + c8 * 8;
            *(uint4*)dst = pk[i];
        }
#pragma unroll
        for (int i = 0; i < 2; i++) {
            const __nv_bfloat16* va = (const __nv_bfloat16*)&pva[i];
            const __nv_bfloat16* vb = (const __nv_bfloat16*)&pvb[i];
            __nv_bfloat16* Vt = (i == 0 ? Vh : Vl);
#pragma unroll
            for (int j = 0; j < 8; j++) {
                __nv_bfloat162 p;
                p.x = va[j]; p.y = vb[j];
                *(__nv_bfloat162*)&Vt[(c8v * 8 + j) * VSTR + 2 * kp] = p;
            }
        }
        __syncthreads();

        // ---- prefetch next tile (overlaps compute below) ----
        if (kt + 1 < nkt) {
            const int kn = (kt + 1) * 64;
#pragma unroll
            for (int i = 0; i < 4; i++) {
                const int idx = tid + (i & 1) * 256;
                const int key = idx >> 3, c8 = idx & 7;
                pk[i] = *(const uint4*)((i < 2 ? g_qkvh : g_qkvl)
                    + (size_t)(b * SEQ + kn + key) * 3072 + 1024 + h * 64 + c8 * 8);
            }
#pragma unroll
            for (int i = 0; i < 2; i++) {
                const __nv_bfloat16* src = (i == 0 ? g_qkvh : g_qkvl)
                    + (size_t)(b * SEQ + kn + 2 * kp) * 3072 + 2048 + h * 64 + c8v * 8;
                pva[i] = *(const uint4*)src;
                pvb[i] = *(const uint4*)(src + 3072);
            }
        }

        if (k0 <= rmax) {
            // ---- QK^T (bf16x3) ----
            float s[8][4];
#pragma unroll
            for (int nt = 0; nt < 8; nt++)
#pragma unroll
                for (int q = 0; q < 4; q++) s[nt][q] = 0.f;

#pragma unroll
            for (int ds = 0; ds < 4; ds++) {
                const int kk = ds * 16 + tg * 2;
#pragma unroll
                for (int nt = 0; nt < 8; nt++) {
                    uint32_t bh[2], bl[2];
                    const int o = (nt * 8 + gi) * KSTR + kk;
                    bh[0] = *(const uint32_t*)&Kh[o];
                    bh[1] = *(const uint32_t*)&Kh[o + 8];
                    bl[0] = *(const uint32_t*)&Kl[o];
                    bl[1] = *(const uint32_t*)&Kl[o + 8];
                    MMA_BF16(s[nt], qh[ds], bh);
                    MMA_BF16(s[nt], qh[ds], bl);
                    MMA_BF16(s[nt], ql[ds], bh);
                }
            }

#pragma unroll
            for (int nt = 0; nt < 8; nt++)
#pragma unroll
                for (int q = 0; q < 4; q++) s[nt][q] *= scl;
            if (kt >= 2 * qt) {
#pragma unroll
                for (int nt = 0; nt < 8; nt++) {
                    const int c0 = k0 + nt * 8 + tg * 2;
                    if (c0     > row0) s[nt][0] = -INFINITY;
                    if (c0 + 1 > row0) s[nt][1] = -INFINITY;
                    if (c0     > row1) s[nt][2] = -INFINITY;
                    if (c0 + 1 > row1) s[nt][3] = -INFINITY;
                }
            }

            // ---- online softmax ----
            float mx0 = -INFINITY, mx1 = -INFINITY;
#pragma unroll
            for (int nt = 0; nt < 8; nt++) {
                mx0 = fmaxf(mx0, fmaxf(s[nt][0], s[nt][1]));
                mx1 = fmaxf(mx1, fmaxf(s[nt][2], s[nt][3]));
            }
            mx0 = fmaxf(mx0, __shfl_xor_sync(0xffffffffu, mx0, 1));
            mx0 = fmaxf(mx0, __shfl_xor_sync(0xffffffffu, mx0, 2));
            mx1 = fmaxf(mx1, __shfl_xor_sync(0xffffffffu, mx1, 1));
            mx1 = fmaxf(mx1, __shfl_xor_sync(0xffffffffu, mx1, 2));

            const float nm0 = fmaxf(m0v, mx0);
            const float nm1 = fmaxf(m1v, mx1);
            const float al0 = __expf(m0v - nm0);
            const float al1 = __expf(m1v - nm1);
            float rs0 = 0.f, rs1 = 0.f;
#pragma unroll
            for (int nt = 0; nt < 8; nt++) {
                s[nt][0] = __expf(s[nt][0] - nm0);
                s[nt][1] = __expf(s[nt][1] - nm0);
                s[nt][2] = __expf(s[nt][2] - nm1);
                s[nt][3] = __expf(s[nt][3] - nm1);
                rs0 += s[nt][0] + s[nt][1];
                rs1 += s[nt][2] + s[nt][3];
            }
            rs0 += __shfl_xor_sync(0xffffffffu, rs0, 1);
            rs0 += __shfl_xor_sync(0xffffffffu, rs0, 2);
            rs1 += __shfl_xor_sync(0xffffffffu, rs1, 1);
            rs1 += __shfl_xor_sync(0xffffffffu, rs1, 2);
            l0v = l0v * al0 + rs0;
            l1v = l1v * al1 + rs1;
            m0v = nm0; m1v = nm1;
#pragma unroll
            for (int nt = 0; nt < 8; nt++) {
                acc_o[nt][0] *= al0; acc_o[nt][1] *= al0;
                acc_o[nt][2] *= al1; acc_o[nt][3] *= al1;
            }

            // ---- PV (bf16x3) ----
#pragma unroll
            for (int s4 = 0; s4 < 4; s4++) {
                uint32_t pa[4], pl[4];
                {
                    const float p00 = s[2 * s4][0],     p01 = s[2 * s4][1];
                    const float p02 = s[2 * s4][2],     p03 = s[2 * s4][3];
                    const float p10 = s[2 * s4 + 1][0], p11 = s[2 * s4 + 1][1];
                    const float p12 = s[2 * s4 + 1][2], p13 = s[2 * s4 + 1][3];
                    pa[0] = pack2bf(p00, p01);
                    pa[1] = pack2bf(p02, p03);
                    pa[2] = pack2bf(p10, p11);
                    pa[3] = pack2bf(p12, p13);
                    __nv_bfloat162* ph;
                    ph = (__nv_bfloat162*)&pa[0];
                    pl[0] = pack2bf(p00 - __bfloat162float(ph->x), p01 - __bfloat162float(ph->y));
                    ph = (__nv_bfloat162*)&pa[1];
                    pl[1] = pack2bf(p02 - __bfloat162float(ph->x), p03 - __bfloat162float(ph->y));
                    ph = (__nv_bfloat162*)&pa[2];
                    pl[2] = pack2bf(p10 - __bfloat162float(ph->x), p11 - __bfloat162float(ph->y));
                    ph = (__nv_bfloat162*)&pa[3];
                    pl[3] = pack2bf(p12 - __bfloat162float(ph->x), p13 - __bfloat162float(ph->y));
                }
                const int kk = s4 * 16 + tg * 2;
#pragma unroll
                for (int nt = 0; nt < 8; nt++) {
                    uint32_t bvh[2], bvl[2];
                    const int o = (nt * 8 + gi) * VSTR + kk;
                    bvh[0] = *(const uint32_t*)&Vh[o];
                    bvh[1] = *(const uint32_t*)&Vh[o + 8];
                    bvl[0] = *(const uint32_t*)&Vl[o];
                    bvl[1] = *(const uint32_t*)&Vl[o + 8];
                    MMA_BF16(acc_o[nt], pa, bvh);
                    MMA_BF16(acc_o[nt], pa, bvl);
                    MMA_BF16(acc_o[nt], pl, bvh);
                }
            }
        }
        __syncthreads();
    }

    // ---- epilogue: split output to bf16 hi/lo ----
    const float inv0 = 1.f / l0v;
    const float inv1 = 1.f / l1v;
#pragma unroll
    for (int nt = 0; nt < 8; nt++) {
        const int col = h * 64 + nt * 8 + tg * 2;
        const float o0 = acc_o[nt][0] * inv0, o1 = acc_o[nt][1] * inv0;
        const float o2 = acc_o[nt][2] * inv1, o3 = acc_o[nt][3] * inv1;
        __nv_bfloat16 h0 = __float2bfloat16(o0);
        __nv_bfloat16 h1 = __float2bfloat16(o1);
        __nv_bfloat16 h2 = __float2bfloat16(o2);
        __nv_bfloat16 h3 = __float2bfloat16(o3);
        const size_t oA = (size_t)(b * SEQ + row0) * HSZ + col;
        const size_t oB = (size_t)(b * SEQ + row1) * HSZ + col;
        *(uint32_t*)&g_atth[oA] = pack2bf(__bfloat162float(h0), __bfloat162float(h1));
        *(uint32_t*)&g_atth[oB] = pack2bf(__bfloat162float(h2), __bfloat162float(h3));
        *(uint32_t*)&g_attl[oA] = pack2bf(o0 - __bfloat162float(h0), o1 - __bfloat162float(h1));
        *(uint32_t*)&g_attl[oB] = pack2bf(o2 - __bfloat162float(h2), o3 - __bfloat162float(h3));
    }
}

// ============================================================
// host launcher
// ============================================================
extern "C" void kernel_launch(void* const* d_in, const int* in_sizes, int n_in,
                              void* d_out, int out_size)
{
    const float* x     = (const float*)d_in[0];
    const float* ln_g  = (const float*)d_in[1];
    const float* ln_b  = (const float*)d_in[2];
    const float* w_qkv = (const float*)d_in[3];
    const float* b_qkv = (const float*)d_in[4];
    const float* w_ent = (const float*)d_in[5];
    const float* b_ent = (const float*)d_in[6];
    const float* w_out = (const float*)d_in[7];
    const float* b_out = (const float*)d_in[8];
    float* out = (float*)d_out;

    void *p_xh, *p_xl, *p_gate, *p_wqh, *p_wql, *p_woh, *p_wol;
    void *p_qkvh, *p_qkvl, *p_atth, *p_attl;
    cudaGetSymbolAddress(&p_xh,   g_xh);
    cudaGetSymbolAddress(&p_xl,   g_xl);
    cudaGetSymbolAddress(&p_gate, g_gate);
    cudaGetSymbolAddress(&p_wqh,  g_wqh);
    cudaGetSymbolAddress(&p_wql,  g_wql);
    cudaGetSymbolAddress(&p_woh,  g_woh);
    cudaGetSymbolAddress(&p_wol,  g_wol);
    cudaGetSymbolAddress(&p_qkvh, g_qkvh);
    cudaGetSymbolAddress(&p_qkvl, g_qkvl);
    cudaGetSymbolAddress(&p_atth, g_atth);
    cudaGetSymbolAddress(&p_attl, g_attl);

    cudaFuncSetAttribute(bf16x3_gemm2, cudaFuncAttributeMaxDynamicSharedMemorySize, G_SMEM);
    cudaFuncSetAttribute(attn_mma, cudaFuncAttributeMaxDynamicSharedMemorySize, ATT_SMEM);

    // 0) pre-split weights
    wsplit<<<(3 * HSZ * HSZ / 4 + 255) / 256, 256>>>(
        w_qkv, (__nv_bfloat16*)p_wqh, (__nv_bfloat16*)p_wql, 3 * HSZ * HSZ / 4);
    wsplit<<<(HSZ * HSZ / 4 + 255) / 256, 256>>>(
        w_out, (__nv_bfloat16*)p_woh, (__nv_bfloat16*)p_wol, HSZ * HSZ / 4);

    // 1) LN + entropy gate (writes split xn)
    ln_gate_kernel<<<NTOK, 256>>>(x, ln_g, ln_b, w_ent, b_ent);

    // 2) QKV projection -> split bf16 qkv, gate folded into V cols
    bf16x3_gemm2<<<dim3(3 * HSZ / 128, NTOK / 128), 256, G_SMEM>>>(
        (const __nv_bfloat16*)p_xh, (const __nv_bfloat16*)p_xl,
        (const __nv_bfloat16*)p_wqh, (const __nv_bfloat16*)p_wql,
        b_qkv, (const float*)p_gate, 2048,
        nullptr, (__nv_bfloat16*)p_qkvh, (__nv_bfloat16*)p_qkvl,
        NTOK, 3 * HSZ, HSZ, 1.0f);

    // 3) attention
    attn_mma<<<dim3(SEQ / 128, NHEADS, BATCH), 256, ATT_SMEM>>>();

    // 4) output projection (fp32 out, alpha=0.1)
    bf16x3_gemm2<<<dim3(HSZ / 128, NTOK / 128), 256, G_SMEM>>>(
        (const __nv_bfloat16*)p_atth, (const __nv_bfloat16*)p_attl,
        (const __nv_bfloat16*)p_woh, (const __nv_bfloat16*)p_wol,
        b_out, nullptr, 1 << 30,
        out, nullptr, nullptr,
        NTOK, HSZ, HSZ, 0.1f);
}